// round 1
// baseline (speedup 1.0000x reference)
#include <cuda_runtime.h>
#include <cuda_bf16.h>
#include <math.h>
#include <stdint.h>

// ---------------------------------------------------------------------------
// Problem constants
// ---------------------------------------------------------------------------
#define QL 2048
#define BSZ 2
#define DM 1024
#define NH 16
#define DH 64
#define DI 4096
#define NTOK (QL*BSZ)          // 4096 rows, row t = i*BSZ + b

// ---------------------------------------------------------------------------
// Scratch (device globals; no allocation allowed)
// ---------------------------------------------------------------------------
__device__ float g_heads[NTOK * 3 * DM];   // qkv projections  [4096, 3072]
__device__ float g_rk[QL * DM];            // r @ r_net_w      [2048, 1024]
__device__ float g_attnvec[NTOK * DM];     // attention output [4096, 1024]
__device__ float g_attnout[NTOK * DM];     // o-proj output
__device__ float g_x[NTOK * DM];           // after LN1
__device__ float g_h[NTOK * DI];           // ffn hidden       [4096, 4096]
__device__ float g_core[NTOK * DM];        // ffn output

// ---------------------------------------------------------------------------
// tf32 helpers
// ---------------------------------------------------------------------------
__device__ __forceinline__ float to_tf32(float v) {
    uint32_t u;
    asm("cvt.rna.tf32.f32 %0, %1;" : "=r"(u) : "f"(v));
    return __uint_as_float(u);
}

#define MMA_TF32(d, a, b)                                                      \
    asm volatile(                                                              \
        "mma.sync.aligned.m16n8k8.row.col.f32.tf32.tf32.f32 "                  \
        "{%0,%1,%2,%3},{%4,%5,%6,%7},{%8,%9},{%0,%1,%2,%3};\n"                 \
        : "+f"(d[0]), "+f"(d[1]), "+f"(d[2]), "+f"(d[3])                       \
        : "r"(a[0]), "r"(a[1]), "r"(a[2]), "r"(a[3]), "r"(b[0]), "r"(b[1]))

// ---------------------------------------------------------------------------
// Generic tf32 GEMM: C[M,N] = A[M,K] @ B[K,N]  (+bias)(+relu per EPI)
// Tile 128x128x32, 256 threads (8 warps: 2 (m) x 4 (n), warp tile 64x32).
// M,N,K must be multiples of 128/128/32 (true for all calls here).
// EPI: 0 = plain store, 1 = bias + relu
// ---------------------------------------------------------------------------
template <int EPI>
__global__ void __launch_bounds__(256)
gemm_tf32(const float* __restrict__ A, const float* __restrict__ B,
          float* __restrict__ C, const float* __restrict__ bias,
          int M, int N, int K)
{
    const int bm = blockIdx.y * 128;
    const int bn = blockIdx.x * 128;

    __shared__ float As[128 * 36];   // stride 36 (pad)
    __shared__ float Bs[32 * 136];   // stride 136 (pad -> conflict-free frags)

    const int tid = threadIdx.x;
    const int w   = tid >> 5;
    const int l   = tid & 31;
    const int g   = l >> 2;   // group id 0..7
    const int t   = l & 3;    // thread-in-group 0..3
    const int wm  = (w & 1) * 64;
    const int wn  = (w >> 1) * 32;

    float c[4][4][4];
    #pragma unroll
    for (int mt = 0; mt < 4; mt++)
        #pragma unroll
        for (int nt = 0; nt < 4; nt++)
            #pragma unroll
            for (int q = 0; q < 4; q++) c[mt][nt][q] = 0.f;

    float4 ra[4], rb[4];

    const int KT = K / 32;

    // global -> regs for k-tile kt
    #define LOAD_G(kt)                                                         \
        {                                                                      \
            const float* Ap = A + (long)bm * K + (kt) * 32;                    \
            _Pragma("unroll")                                                  \
            for (int it = 0; it < 4; it++) {                                   \
                int f = tid + it * 256;                                        \
                int rr = f >> 3, c4 = f & 7;                                   \
                ra[it] = *(const float4*)(Ap + (long)rr * K + c4 * 4);         \
            }                                                                  \
            const float* Bp = B + (long)(kt) * 32 * N + bn;                    \
            _Pragma("unroll")                                                  \
            for (int it = 0; it < 4; it++) {                                   \
                int f = tid + it * 256;                                        \
                int rr = f >> 5, c4 = f & 31;                                  \
                rb[it] = *(const float4*)(Bp + (long)rr * N + c4 * 4);         \
            }                                                                  \
        }

    // regs -> smem (with tf32 rounding)
    #define STORE_S()                                                          \
        {                                                                      \
            _Pragma("unroll")                                                  \
            for (int it = 0; it < 4; it++) {                                   \
                int f = tid + it * 256;                                        \
                int rr = f >> 3, c4 = f & 7;                                   \
                float* p = As + rr * 36 + c4 * 4;                              \
                p[0] = to_tf32(ra[it].x); p[1] = to_tf32(ra[it].y);            \
                p[2] = to_tf32(ra[it].z); p[3] = to_tf32(ra[it].w);            \
            }                                                                  \
            _Pragma("unroll")                                                  \
            for (int it = 0; it < 4; it++) {                                   \
                int f = tid + it * 256;                                        \
                int rr = f >> 5, c4 = f & 31;                                  \
                float* p = Bs + rr * 136 + c4 * 4;                             \
                p[0] = to_tf32(rb[it].x); p[1] = to_tf32(rb[it].y);            \
                p[2] = to_tf32(rb[it].z); p[3] = to_tf32(rb[it].w);            \
            }                                                                  \
        }

    LOAD_G(0);
    STORE_S();
    __syncthreads();

    for (int kt = 0; kt < KT; kt++) {
        if (kt + 1 < KT) LOAD_G(kt + 1);

        #pragma unroll
        for (int ks = 0; ks < 4; ks++) {
            uint32_t af[4][4], bf[4][2];
            #pragma unroll
            for (int mt = 0; mt < 4; mt++) {
                const float* ap = As + (wm + mt * 16) * 36 + ks * 8;
                af[mt][0] = __float_as_uint(ap[g * 36 + t]);
                af[mt][1] = __float_as_uint(ap[(g + 8) * 36 + t]);
                af[mt][2] = __float_as_uint(ap[g * 36 + t + 4]);
                af[mt][3] = __float_as_uint(ap[(g + 8) * 36 + t + 4]);
            }
            #pragma unroll
            for (int nt = 0; nt < 4; nt++) {
                const float* bp = Bs + (ks * 8) * 136 + wn + nt * 8;
                bf[nt][0] = __float_as_uint(bp[t * 136 + g]);
                bf[nt][1] = __float_as_uint(bp[(t + 4) * 136 + g]);
            }
            #pragma unroll
            for (int mt = 0; mt < 4; mt++)
                #pragma unroll
                for (int nt = 0; nt < 4; nt++)
                    MMA_TF32(c[mt][nt], af[mt], bf[nt]);
        }

        __syncthreads();
        if (kt + 1 < KT) {
            STORE_S();
            __syncthreads();
        }
    }

    // epilogue
    #pragma unroll
    for (int mt = 0; mt < 4; mt++) {
        #pragma unroll
        for (int nt = 0; nt < 4; nt++) {
            int row0 = bm + wm + mt * 16 + g;
            int col  = bn + wn + nt * 8 + 2 * t;
            float v0 = c[mt][nt][0], v1 = c[mt][nt][1];
            float v2 = c[mt][nt][2], v3 = c[mt][nt][3];
            if (EPI == 1) {
                float b0 = bias[col], b1 = bias[col + 1];
                v0 = fmaxf(v0 + b0, 0.f); v1 = fmaxf(v1 + b1, 0.f);
                v2 = fmaxf(v2 + b0, 0.f); v3 = fmaxf(v3 + b1, 0.f);
            }
            float2 p01 = make_float2(v0, v1);
            float2 p23 = make_float2(v2, v3);
            *(float2*)(C + (long)row0 * N + col)       = p01;
            *(float2*)(C + (long)(row0 + 8) * N + col) = p23;
        }
    }
    #undef LOAD_G
    #undef STORE_S
}

// ---------------------------------------------------------------------------
// Flash-style causal rel-attention.
// grid (32 qtiles, 16 heads, 2 batch), 256 threads (8 warps).
// Warp w owns query rows ti in [8w, 8w+8); lane owns cols {l, l+32}.
// S[i,j] = (q_i+rwb)·k_j + (q_i+rrb)·rk[QL-1-(i-j)],  scaled, causal-masked.
// ---------------------------------------------------------------------------
__global__ void __launch_bounds__(256, 1)
attn_kernel(const float* __restrict__ rwb, const float* __restrict__ rrb)
{
    extern __shared__ float sm[];
    float* QW = sm;                 // 64*64  (q + r_w_bias)
    float* QR = sm + 4096;          // 64*64  (q + r_r_bias)
    float* Kt = sm + 8192;          // 64*65  (Kt[d][tj])
    float* Vs = sm + 12352;         // 64*64  (Vs[tj][d])
    float* Rt = sm + 16448;         // 64*129 (Rt[d][m_local])
    float* Ps = sm + 24704;         // 64*64

    const int qt = blockIdx.x;
    const int n  = blockIdx.y;
    const int b  = blockIdx.z;
    const int i0 = qt * 64;
    const int tid = threadIdx.x;
    const int w = tid >> 5, l = tid & 31;

    // load Q tile, add biases
    for (int f = tid; f < 64 * 64; f += 256) {
        int ti = f >> 6, d = f & 63;
        float q = g_heads[(long)((i0 + ti) * BSZ + b) * (3 * DM) + n * DH + d];
        QW[f] = q + rwb[n * DH + d];
        QR[f] = q + rrb[n * DH + d];
    }

    float O[8][2], mrow[8], lrow[8];
    #pragma unroll
    for (int s = 0; s < 8; s++) {
        O[s][0] = O[s][1] = 0.f;
        mrow[s] = -INFINITY;
        lrow[s] = 0.f;
    }

    const int ntiles = qt + 1;
    for (int jt = 0; jt < ntiles; jt++) {
        const int j0 = jt * 64;
        __syncthreads();
        // K (transposed), V
        for (int f = tid; f < 64 * 64; f += 256) {
            int tj = f >> 6, d = f & 63;
            long row = (long)((j0 + tj) * BSZ + b) * (3 * DM);
            Kt[d * 65 + tj] = g_heads[row + DM + n * DH + d];
            Vs[f]           = g_heads[row + 2 * DM + n * DH + d];
        }
        // rel-pos slab: rows m = QL-1-(i)+(j); m_local = (63-ti)+tj
        const int mmin = QL - 64 - i0 + j0;
        for (int f = tid; f < 128 * 64; f += 256) {
            int ml = f >> 6, d = f & 63;
            int m = mmin + ml;
            Rt[d * 129 + ml] = (m >= 0 && m < QL) ? g_rk[(long)m * DM + n * DH + d] : 0.f;
        }
        __syncthreads();

        float S[8][2];
        #pragma unroll
        for (int s = 0; s < 8; s++) S[s][0] = S[s][1] = 0.f;

        const float* qwB = QW + w * 8 * 64;
        const float* qrB = QR + w * 8 * 64;

        #pragma unroll 2
        for (int d = 0; d < 64; d++) {
            float k0 = Kt[d * 65 + l];
            float k1 = Kt[d * 65 + 32 + l];
            const float* rp = Rt + d * 129 + 63 - w * 8 + l;
            #pragma unroll
            for (int s = 0; s < 8; s++) {
                float qw = qwB[s * 64 + d];
                float qr = qrB[s * 64 + d];
                S[s][0] += qw * k0 + qr * rp[-s];
                S[s][1] += qw * k1 + qr * rp[32 - s];
            }
        }

        const bool diag = (j0 == i0);
        #pragma unroll
        for (int s = 0; s < 8; s++) {
            int ti = w * 8 + s;
            float s0 = S[s][0] * 0.125f;
            float s1 = S[s][1] * 0.125f;
            if (diag) {
                if (l > ti)      s0 = -INFINITY;
                if (l + 32 > ti) s1 = -INFINITY;
            }
            float rm = fmaxf(s0, s1);
            #pragma unroll
            for (int off = 16; off; off >>= 1)
                rm = fmaxf(rm, __shfl_xor_sync(0xffffffffu, rm, off));
            float mnew = fmaxf(mrow[s], rm);
            float corr = __expf(mrow[s] - mnew);
            float p0 = __expf(s0 - mnew);
            float p1 = __expf(s1 - mnew);
            float rs = p0 + p1;
            #pragma unroll
            for (int off = 16; off; off >>= 1)
                rs += __shfl_xor_sync(0xffffffffu, rs, off);
            lrow[s] = lrow[s] * corr + rs;
            mrow[s] = mnew;
            O[s][0] *= corr;
            O[s][1] *= corr;
            Ps[ti * 64 + l]      = p0;
            Ps[ti * 64 + 32 + l] = p1;
        }
        __syncwarp();

        #pragma unroll 4
        for (int tj = 0; tj < 64; tj++) {
            float v0 = Vs[tj * 64 + l];
            float v1 = Vs[tj * 64 + 32 + l];
            #pragma unroll
            for (int s = 0; s < 8; s++) {
                float p = Ps[(w * 8 + s) * 64 + tj];
                O[s][0] += p * v0;
                O[s][1] += p * v1;
            }
        }
    }

    #pragma unroll
    for (int s = 0; s < 8; s++) {
        int ti = w * 8 + s;
        long row = (long)((i0 + ti) * BSZ + b) * DM;
        float inv = 1.f / lrow[s];
        g_attnvec[row + n * DH + l]      = O[s][0] * inv;
        g_attnvec[row + n * DH + 32 + l] = O[s][1] * inv;
    }
}

// ---------------------------------------------------------------------------
// Residual add (+optional bias) + LayerNorm, one row (1024) per block.
// ---------------------------------------------------------------------------
__global__ void __launch_bounds__(256)
ln_kernel(const float* __restrict__ resid, const float* __restrict__ y,
          const float* __restrict__ bias, const float* __restrict__ gam,
          const float* __restrict__ bet, float* __restrict__ out)
{
    const int row = blockIdx.x;
    const int tid = threadIdx.x;
    __shared__ float buf[DM];
    __shared__ float red[8];

    float lsum = 0.f;
    for (int d = tid; d < DM; d += 256) {
        float v = resid[(long)row * DM + d] + y[(long)row * DM + d];
        if (bias) v += bias[d];
        buf[d] = v;
        lsum += v;
    }
    #pragma unroll
    for (int off = 16; off; off >>= 1) lsum += __shfl_xor_sync(0xffffffffu, lsum, off);
    if ((tid & 31) == 0) red[tid >> 5] = lsum;
    __syncthreads();
    float tot = 0.f;
    #pragma unroll
    for (int i = 0; i < 8; i++) tot += red[i];
    const float mean = tot * (1.f / DM);
    __syncthreads();

    float lv = 0.f;
    for (int d = tid; d < DM; d += 256) {
        float t = buf[d] - mean;
        lv += t * t;
    }
    #pragma unroll
    for (int off = 16; off; off >>= 1) lv += __shfl_xor_sync(0xffffffffu, lv, off);
    if ((tid & 31) == 0) red[tid >> 5] = lv;
    __syncthreads();
    float vtot = 0.f;
    #pragma unroll
    for (int i = 0; i < 8; i++) vtot += red[i];
    const float inv = rsqrtf(vtot * (1.f / DM) + 1e-5f);

    for (int d = tid; d < DM; d += 256)
        out[(long)row * DM + d] = (buf[d] - mean) * inv * gam[d] + bet[d];
}

// ---------------------------------------------------------------------------
// Host launch
// ---------------------------------------------------------------------------
extern "C" void kernel_launch(void* const* d_in, const int* in_sizes, int n_in,
                              void* d_out, int out_size)
{
    const float* w      = (const float*)d_in[0];
    const float* r      = (const float*)d_in[1];
    const float* rwb    = (const float*)d_in[2];
    const float* rrb    = (const float*)d_in[3];
    // d_in[4] = attn_mask (causal triu, recomputed implicitly)
    const float* qkv_w  = (const float*)d_in[5];
    const float* rnet_w = (const float*)d_in[6];
    const float* o_w    = (const float*)d_in[7];
    const float* ln1_g  = (const float*)d_in[8];
    const float* ln1_b  = (const float*)d_in[9];
    const float* ffn_w1 = (const float*)d_in[10];
    const float* ffn_b1 = (const float*)d_in[11];
    const float* ffn_w2 = (const float*)d_in[12];
    const float* ffn_b2 = (const float*)d_in[13];
    const float* ln2_g  = (const float*)d_in[14];
    const float* ln2_b  = (const float*)d_in[15];

    float *heads, *rk, *attnvec, *attnout, *x, *h, *core;
    cudaGetSymbolAddress((void**)&heads,   g_heads);
    cudaGetSymbolAddress((void**)&rk,      g_rk);
    cudaGetSymbolAddress((void**)&attnvec, g_attnvec);
    cudaGetSymbolAddress((void**)&attnout, g_attnout);
    cudaGetSymbolAddress((void**)&x,       g_x);
    cudaGetSymbolAddress((void**)&h,       g_h);
    cudaGetSymbolAddress((void**)&core,    g_core);

    // 1) qkv projection: [4096,1024] @ [1024,3072]
    gemm_tf32<0><<<dim3(3 * DM / 128, NTOK / 128), 256>>>(w, qkv_w, heads, nullptr,
                                                          NTOK, 3 * DM, DM);
    // 2) r_k: [2048,1024] @ [1024,1024]
    gemm_tf32<0><<<dim3(DM / 128, QL / 128), 256>>>(r, rnet_w, rk, nullptr,
                                                    QL, DM, DM);
    // 3) attention
    {
        const int smem = (4096 * 4 + 64 * 65 + 64 * 129) * (int)sizeof(float); // 115200
        cudaFuncSetAttribute(attn_kernel, cudaFuncAttributeMaxDynamicSharedMemorySize, smem);
        attn_kernel<<<dim3(QL / 64, NH, BSZ), 256, smem>>>(rwb, rrb);
    }
    // 4) o projection
    gemm_tf32<0><<<dim3(DM / 128, NTOK / 128), 256>>>(attnvec, o_w, attnout, nullptr,
                                                      NTOK, DM, DM);
    // 5) x = LN(w + attn_out)
    ln_kernel<<<NTOK, 256>>>(w, attnout, nullptr, ln1_g, ln1_b, x);
    // 6) h = relu(x @ ffn_w1 + b1)
    gemm_tf32<1><<<dim3(DI / 128, NTOK / 128), 256>>>(x, ffn_w1, h, ffn_b1,
                                                      NTOK, DI, DM);
    // 7) core = h @ ffn_w2  (bias b2 added in LN)
    gemm_tf32<0><<<dim3(DM / 128, NTOK / 128), 256>>>(h, ffn_w2, core, nullptr,
                                                      NTOK, DM, DI);
    // 8) out = LN(x + core + b2)
    ln_kernel<<<NTOK, 256>>>(x, core, ffn_b2, ln2_g, ln2_b, (float*)d_out);
}

// round 4
// speedup vs baseline: 1.3694x; 1.3694x over previous
#include <cuda_runtime.h>
#include <cuda_bf16.h>
#include <math.h>
#include <stdint.h>

// ---------------------------------------------------------------------------
// Problem constants
// ---------------------------------------------------------------------------
#define QL 2048
#define BSZ 2
#define DM 1024
#define NH 16
#define DH 64
#define DI 4096
#define NTOK (QL*BSZ)          // 4096 rows, row t = i*BSZ + b

// ---------------------------------------------------------------------------
// Scratch (device globals; no allocation allowed)
// ---------------------------------------------------------------------------
__device__ float g_heads[NTOK * 3 * DM];   // qkv projections  [4096, 3072]
__device__ float g_rk[QL * DM];            // r @ r_net_w      [2048, 1024]
__device__ float g_attnvec[NTOK * DM];     // attention output [4096, 1024]
__device__ float g_attnout[NTOK * DM];     // o-proj output
__device__ float g_x[NTOK * DM];           // after LN1
__device__ float g_h[NTOK * DI];           // ffn hidden       [4096, 4096]
__device__ float g_core[NTOK * DM];        // ffn output

// ---------------------------------------------------------------------------
// tf32 helpers
// ---------------------------------------------------------------------------
__device__ __forceinline__ float to_tf32(float v) {
    uint32_t u;
    asm("cvt.rna.tf32.f32 %0, %1;" : "=r"(u) : "f"(v));
    return __uint_as_float(u);
}

#define MMA_TF32(d, a, b)                                                      \
    asm volatile(                                                              \
        "mma.sync.aligned.m16n8k8.row.col.f32.tf32.tf32.f32 "                  \
        "{%0,%1,%2,%3},{%4,%5,%6,%7},{%8,%9},{%0,%1,%2,%3};\n"                 \
        : "+f"(d[0]), "+f"(d[1]), "+f"(d[2]), "+f"(d[3])                       \
        : "r"(a[0]), "r"(a[1]), "r"(a[2]), "r"(a[3]), "r"(b[0]), "r"(b[1]))

// ---------------------------------------------------------------------------
// Generic tf32 GEMM: C[M,N] = A[M,K] @ B[K,N]  (+bias)(+relu per EPI)
// Tile 128x128x32, 256 threads (8 warps: 2 (m) x 4 (n), warp tile 64x32).
// EPI: 0 = plain store, 1 = bias + relu
// ---------------------------------------------------------------------------
template <int EPI>
__global__ void __launch_bounds__(256)
gemm_tf32(const float* __restrict__ A, const float* __restrict__ B,
          float* __restrict__ C, const float* __restrict__ bias,
          int M, int N, int K)
{
    const int bm = blockIdx.y * 128;
    const int bn = blockIdx.x * 128;

    __shared__ float As[128 * 36];   // stride 36 (pad)
    __shared__ float Bs[32 * 136];   // stride 136 (pad -> conflict-free frags)

    const int tid = threadIdx.x;
    const int w   = tid >> 5;
    const int l   = tid & 31;
    const int g   = l >> 2;   // group id 0..7
    const int t   = l & 3;    // thread-in-group 0..3
    const int wm  = (w & 1) * 64;
    const int wn  = (w >> 1) * 32;

    float c[4][4][4];
    #pragma unroll
    for (int mt = 0; mt < 4; mt++)
        #pragma unroll
        for (int nt = 0; nt < 4; nt++)
            #pragma unroll
            for (int q = 0; q < 4; q++) c[mt][nt][q] = 0.f;

    float4 ra[4], rb[4];

    const int KT = K / 32;

    #define LOAD_G(kt)                                                         \
        {                                                                      \
            const float* Ap = A + (long)bm * K + (kt) * 32;                    \
            _Pragma("unroll")                                                  \
            for (int it = 0; it < 4; it++) {                                   \
                int f = tid + it * 256;                                        \
                int rr = f >> 3, c4 = f & 7;                                   \
                ra[it] = *(const float4*)(Ap + (long)rr * K + c4 * 4);         \
            }                                                                  \
            const float* Bp = B + (long)(kt) * 32 * N + bn;                    \
            _Pragma("unroll")                                                  \
            for (int it = 0; it < 4; it++) {                                   \
                int f = tid + it * 256;                                        \
                int rr = f >> 5, c4 = f & 31;                                  \
                rb[it] = *(const float4*)(Bp + (long)rr * N + c4 * 4);         \
            }                                                                  \
        }

    #define STORE_S()                                                          \
        {                                                                      \
            _Pragma("unroll")                                                  \
            for (int it = 0; it < 4; it++) {                                   \
                int f = tid + it * 256;                                        \
                int rr = f >> 3, c4 = f & 7;                                   \
                float* p = As + rr * 36 + c4 * 4;                              \
                p[0] = to_tf32(ra[it].x); p[1] = to_tf32(ra[it].y);            \
                p[2] = to_tf32(ra[it].z); p[3] = to_tf32(ra[it].w);            \
            }                                                                  \
            _Pragma("unroll")                                                  \
            for (int it = 0; it < 4; it++) {                                   \
                int f = tid + it * 256;                                        \
                int rr = f >> 5, c4 = f & 31;                                  \
                float* p = Bs + rr * 136 + c4 * 4;                             \
                p[0] = to_tf32(rb[it].x); p[1] = to_tf32(rb[it].y);            \
                p[2] = to_tf32(rb[it].z); p[3] = to_tf32(rb[it].w);            \
            }                                                                  \
        }

    LOAD_G(0);
    STORE_S();
    __syncthreads();

    for (int kt = 0; kt < KT; kt++) {
        if (kt + 1 < KT) LOAD_G(kt + 1);

        #pragma unroll
        for (int ks = 0; ks < 4; ks++) {
            uint32_t af[4][4], bf[4][2];
            #pragma unroll
            for (int mt = 0; mt < 4; mt++) {
                const float* ap = As + (wm + mt * 16) * 36 + ks * 8;
                af[mt][0] = __float_as_uint(ap[g * 36 + t]);
                af[mt][1] = __float_as_uint(ap[(g + 8) * 36 + t]);
                af[mt][2] = __float_as_uint(ap[g * 36 + t + 4]);
                af[mt][3] = __float_as_uint(ap[(g + 8) * 36 + t + 4]);
            }
            #pragma unroll
            for (int nt = 0; nt < 4; nt++) {
                const float* bp = Bs + (ks * 8) * 136 + wn + nt * 8;
                bf[nt][0] = __float_as_uint(bp[t * 136 + g]);
                bf[nt][1] = __float_as_uint(bp[(t + 4) * 136 + g]);
            }
            #pragma unroll
            for (int mt = 0; mt < 4; mt++)
                #pragma unroll
                for (int nt = 0; nt < 4; nt++)
                    MMA_TF32(c[mt][nt], af[mt], bf[nt]);
        }

        __syncthreads();
        if (kt + 1 < KT) {
            STORE_S();
            __syncthreads();
        }
    }

    #pragma unroll
    for (int mt = 0; mt < 4; mt++) {
        #pragma unroll
        for (int nt = 0; nt < 4; nt++) {
            int row0 = bm + wm + mt * 16 + g;
            int col  = bn + wn + nt * 8 + 2 * t;
            float v0 = c[mt][nt][0], v1 = c[mt][nt][1];
            float v2 = c[mt][nt][2], v3 = c[mt][nt][3];
            if (EPI == 1) {
                float b0 = bias[col], b1 = bias[col + 1];
                v0 = fmaxf(v0 + b0, 0.f); v1 = fmaxf(v1 + b1, 0.f);
                v2 = fmaxf(v2 + b0, 0.f); v3 = fmaxf(v3 + b1, 0.f);
            }
            float2 p01 = make_float2(v0, v1);
            float2 p23 = make_float2(v2, v3);
            *(float2*)(C + (long)row0 * N + col)       = p01;
            *(float2*)(C + (long)(row0 + 8) * N + col) = p23;
        }
    }
    #undef LOAD_G
    #undef STORE_S
}

// ---------------------------------------------------------------------------
// MMA-based flash causal rel-attention.
// grid (32 qtiles [longest first], 16 heads, 2 batch), 256 threads (8 warps).
// Per j-tile:
//   S = (Q+rwb) Kt^T   (64x64x64 tf32 mma)
//   G = (Q+rrb) R2^T   (64x128x64 tf32 mma over rel-pos slab)
//   softmax over S[ti][tj] + G[ti][63-ti+tj] (shift-gather), online
//   O += P V           (64x64x64 tf32 mma)
// mma warp layout: warp w -> rows 16*(w>>1).., cols 32*(w&1)..
// softmax warp layout: warp w -> rows 8w..8w+7, lane l -> cols {l, l+32}
// ---------------------------------------------------------------------------
#define ATT_STR 68     // 64 + 4 pad: banks of frag loads = (4g+t)%32, conflict-free
#define GS_STR 132     // 128 + 4 pad

__global__ void __launch_bounds__(256, 1)
attn_mma_kernel(const float* __restrict__ rwb, const float* __restrict__ rrb)
{
    extern __shared__ float sm[];
    float* QW = sm;                      // 64*68
    float* QR = QW + 64 * ATT_STR;       // 64*68
    float* Ks = QR + 64 * ATT_STR;       // 64*68 Ks[tj][d]
    float* Vs = Ks + 64 * ATT_STR;       // 64*68 Vs[tj][d]
    float* Rs = Vs + 64 * ATT_STR;       // 128*68 Rs[ml][d]
    float* SP = Rs + 128 * ATT_STR;      // 64*68 S then P (in place)
    float* Gs = SP + 64 * ATT_STR;       // 64*132
    float* corr_s = Gs + 64 * GS_STR;    // 64
    float* linv_s = corr_s + 64;         // 64

    const int qt = 31 - (int)blockIdx.x; // longest q-tiles launch first
    const int n  = blockIdx.y;
    const int b  = blockIdx.z;
    const int i0 = qt * 64;
    const int tid = threadIdx.x;
    const int w = tid >> 5, l = tid & 31;
    const int g = l >> 2, t = l & 3;
    const int roff = (w >> 1) * 16;      // mma row offset
    const int coff = (w & 1) * 32;       // mma col offset
    const float scale = 0.125f;

    // Load Q tile + biases (once per block)
    for (int f = tid; f < 64 * 16; f += 256) {
        int ti = f >> 4, d4 = (f & 15) * 4;
        float4 q  = *(const float4*)&g_heads[(size_t)((i0 + ti) * BSZ + b) * (3 * DM) + n * DH + d4];
        float4 wb = *(const float4*)&rwb[n * DH + d4];
        float4 rb = *(const float4*)&rrb[n * DH + d4];
        float* pw = QW + ti * ATT_STR + d4;
        float* pr = QR + ti * ATT_STR + d4;
        pw[0] = to_tf32(q.x + wb.x); pw[1] = to_tf32(q.y + wb.y);
        pw[2] = to_tf32(q.z + wb.z); pw[3] = to_tf32(q.w + wb.w);
        pr[0] = to_tf32(q.x + rb.x); pr[1] = to_tf32(q.y + rb.y);
        pr[2] = to_tf32(q.z + rb.z); pr[3] = to_tf32(q.w + rb.w);
    }

    float O[4][4];
    #pragma unroll
    for (int nt = 0; nt < 4; nt++)
        #pragma unroll
        for (int q = 0; q < 4; q++) O[nt][q] = 0.f;
    float mrow[8], lrow[8];
    #pragma unroll
    for (int s = 0; s < 8; s++) { mrow[s] = -INFINITY; lrow[s] = 0.f; }

    for (int jt = 0; jt <= qt; jt++) {
        const int j0 = jt * 64;
        __syncthreads();  // protect smem from previous iter's readers

        // K, V tiles
        for (int f = tid; f < 64 * 16; f += 256) {
            int tj = f >> 4, d4 = (f & 15) * 4;
            size_t base = (size_t)((j0 + tj) * BSZ + b) * (3 * DM) + n * DH + d4;
            float4 kv = *(const float4*)&g_heads[base + DM];
            float4 vv = *(const float4*)&g_heads[base + 2 * DM];
            float* pk = Ks + tj * ATT_STR + d4;
            float* pv = Vs + tj * ATT_STR + d4;
            pk[0] = to_tf32(kv.x); pk[1] = to_tf32(kv.y);
            pk[2] = to_tf32(kv.z); pk[3] = to_tf32(kv.w);
            pv[0] = to_tf32(vv.x); pv[1] = to_tf32(vv.y);
            pv[2] = to_tf32(vv.z); pv[3] = to_tf32(vv.w);
        }
        // rel-pos slab: row ml holds rk[mmin+ml]; BD[ti][tj] uses ml = 63-ti+tj
        const int mmin = QL - 64 - i0 + j0;
        for (int f = tid; f < 128 * 16; f += 256) {
            int ml = f >> 4, d4 = (f & 15) * 4;
            int m = mmin + ml;
            float* p = Rs + ml * ATT_STR + d4;
            if (m >= 0 && m < QL) {
                float4 rv = *(const float4*)&g_rk[(size_t)m * DM + n * DH + d4];
                p[0] = to_tf32(rv.x); p[1] = to_tf32(rv.y);
                p[2] = to_tf32(rv.z); p[3] = to_tf32(rv.w);
            } else {
                p[0] = 0.f; p[1] = 0.f; p[2] = 0.f; p[3] = 0.f;
            }
        }
        __syncthreads();

        // --- S = QW @ K^T ; G = QR @ R2^T ---
        float sc[4][4], gc[8][4];
        #pragma unroll
        for (int nt = 0; nt < 4; nt++)
            #pragma unroll
            for (int q = 0; q < 4; q++) sc[nt][q] = 0.f;
        #pragma unroll
        for (int nt = 0; nt < 8; nt++)
            #pragma unroll
            for (int q = 0; q < 4; q++) gc[nt][q] = 0.f;

        #pragma unroll
        for (int ks = 0; ks < 8; ks++) {
            const int ko = ks * 8;
            uint32_t aw[4], ar[4];
            {
                const float* qa = QW + (roff + g) * ATT_STR + ko + t;
                aw[0] = __float_as_uint(qa[0]);
                aw[1] = __float_as_uint(qa[8 * ATT_STR]);
                aw[2] = __float_as_uint(qa[4]);
                aw[3] = __float_as_uint(qa[8 * ATT_STR + 4]);
                const float* qr = QR + (roff + g) * ATT_STR + ko + t;
                ar[0] = __float_as_uint(qr[0]);
                ar[1] = __float_as_uint(qr[8 * ATT_STR]);
                ar[2] = __float_as_uint(qr[4]);
                ar[3] = __float_as_uint(qr[8 * ATT_STR + 4]);
            }
            #pragma unroll
            for (int nt = 0; nt < 4; nt++) {
                const float* kp = Ks + (coff + nt * 8 + g) * ATT_STR + ko + t;
                uint32_t bf[2] = { __float_as_uint(kp[0]), __float_as_uint(kp[4]) };
                MMA_TF32(sc[nt], aw, bf);
            }
            #pragma unroll
            for (int nt = 0; nt < 8; nt++) {
                const float* rp = Rs + ((w & 1) * 64 + nt * 8 + g) * ATT_STR + ko + t;
                uint32_t bf[2] = { __float_as_uint(rp[0]), __float_as_uint(rp[4]) };
                MMA_TF32(gc[nt], ar, bf);
            }
        }
        // write S (scaled) and G (scaled) to smem
        #pragma unroll
        for (int nt = 0; nt < 4; nt++) {
            float* p = SP + (roff + g) * ATT_STR + coff + nt * 8 + 2 * t;
            p[0] = sc[nt][0] * scale; p[1] = sc[nt][1] * scale;
            p[8 * ATT_STR] = sc[nt][2] * scale; p[8 * ATT_STR + 1] = sc[nt][3] * scale;
        }
        #pragma unroll
        for (int nt = 0; nt < 8; nt++) {
            float* p = Gs + (roff + g) * GS_STR + (w & 1) * 64 + nt * 8 + 2 * t;
            p[0] = gc[nt][0] * scale; p[1] = gc[nt][1] * scale;
            p[8 * GS_STR] = gc[nt][2] * scale; p[8 * GS_STR + 1] = gc[nt][3] * scale;
        }
        __syncthreads();

        // --- online softmax: warp w rows 8w..8w+7, lane cols {l, l+32} ---
        const bool diag = (jt == qt);
        #pragma unroll
        for (int s = 0; s < 8; s++) {
            const int ti = w * 8 + s;
            float s0 = SP[ti * ATT_STR + l]      + Gs[ti * GS_STR + 63 - ti + l];
            float s1 = SP[ti * ATT_STR + 32 + l] + Gs[ti * GS_STR + 63 - ti + 32 + l];
            if (diag) {
                if (l > ti)      s0 = -INFINITY;
                if (l + 32 > ti) s1 = -INFINITY;
            }
            float rm = fmaxf(s0, s1);
            #pragma unroll
            for (int off = 16; off; off >>= 1)
                rm = fmaxf(rm, __shfl_xor_sync(0xffffffffu, rm, off));
            float mnew = fmaxf(mrow[s], rm);
            float corr = __expf(mrow[s] - mnew);
            float p0 = __expf(s0 - mnew);
            float p1 = __expf(s1 - mnew);
            float rs = p0 + p1;
            #pragma unroll
            for (int off = 16; off; off >>= 1)
                rs += __shfl_xor_sync(0xffffffffu, rs, off);
            lrow[s] = lrow[s] * corr + rs;
            mrow[s] = mnew;
            SP[ti * ATT_STR + l]      = to_tf32(p0);
            SP[ti * ATT_STR + 32 + l] = to_tf32(p1);
            if (l == 0) corr_s[ti] = corr;
        }
        __syncthreads();

        // --- O = O*corr + P @ V ---
        {
            float c0 = corr_s[roff + g], c1 = corr_s[roff + g + 8];
            #pragma unroll
            for (int nt = 0; nt < 4; nt++) {
                O[nt][0] *= c0; O[nt][1] *= c0;
                O[nt][2] *= c1; O[nt][3] *= c1;
            }
        }
        #pragma unroll
        for (int ks = 0; ks < 8; ks++) {
            const int ko = ks * 8;
            uint32_t ap[4];
            const float* pp = SP + (roff + g) * ATT_STR + ko + t;
            ap[0] = __float_as_uint(pp[0]);
            ap[1] = __float_as_uint(pp[8 * ATT_STR]);
            ap[2] = __float_as_uint(pp[4]);
            ap[3] = __float_as_uint(pp[8 * ATT_STR + 4]);
            #pragma unroll
            for (int nt = 0; nt < 4; nt++) {
                const float* vp = Vs + (ko + t) * ATT_STR + coff + nt * 8 + g;
                uint32_t bf[2] = { __float_as_uint(vp[0]), __float_as_uint(vp[4 * ATT_STR]) };
                MMA_TF32(O[nt], ap, bf);
            }
        }
    }

    // final normalization
    #pragma unroll
    for (int s = 0; s < 8; s++)
        if (l == 0) linv_s[w * 8 + s] = 1.f / lrow[s];
    __syncthreads();

    #pragma unroll
    for (int nt = 0; nt < 4; nt++) {
        const int col = n * DH + coff + nt * 8 + 2 * t;
        const int r0 = roff + g, r1 = roff + g + 8;
        const float li0 = linv_s[r0], li1 = linv_s[r1];
        size_t ro0 = (size_t)((i0 + r0) * BSZ + b) * DM;
        size_t ro1 = (size_t)((i0 + r1) * BSZ + b) * DM;
        float2 o0 = make_float2(O[nt][0] * li0, O[nt][1] * li0);
        float2 o1 = make_float2(O[nt][2] * li1, O[nt][3] * li1);
        *(float2*)&g_attnvec[ro0 + col] = o0;
        *(float2*)&g_attnvec[ro1 + col] = o1;
    }
}

// ---------------------------------------------------------------------------
// Residual add (+optional bias) + LayerNorm, one row (1024) per block.
// ---------------------------------------------------------------------------
__global__ void __launch_bounds__(256)
ln_kernel(const float* __restrict__ resid, const float* __restrict__ y,
          const float* __restrict__ bias, const float* __restrict__ gam,
          const float* __restrict__ bet, float* __restrict__ out)
{
    const int row = blockIdx.x;
    const int tid = threadIdx.x;
    __shared__ float buf[DM];
    __shared__ float red[8];

    float lsum = 0.f;
    for (int d = tid; d < DM; d += 256) {
        float v = resid[(long)row * DM + d] + y[(long)row * DM + d];
        if (bias) v += bias[d];
        buf[d] = v;
        lsum += v;
    }
    #pragma unroll
    for (int off = 16; off; off >>= 1) lsum += __shfl_xor_sync(0xffffffffu, lsum, off);
    if ((tid & 31) == 0) red[tid >> 5] = lsum;
    __syncthreads();
    float tot = 0.f;
    #pragma unroll
    for (int i = 0; i < 8; i++) tot += red[i];
    const float mean = tot * (1.f / DM);
    __syncthreads();

    float lv = 0.f;
    for (int d = tid; d < DM; d += 256) {
        float t = buf[d] - mean;
        lv += t * t;
    }
    #pragma unroll
    for (int off = 16; off; off >>= 1) lv += __shfl_xor_sync(0xffffffffu, lv, off);
    if ((tid & 31) == 0) red[tid >> 5] = lv;
    __syncthreads();
    float vtot = 0.f;
    #pragma unroll
    for (int i = 0; i < 8; i++) vtot += red[i];
    const float inv = rsqrtf(vtot * (1.f / DM) + 1e-5f);

    for (int d = tid; d < DM; d += 256)
        out[(long)row * DM + d] = (buf[d] - mean) * inv * gam[d] + bet[d];
}

// ---------------------------------------------------------------------------
// Host launch
// ---------------------------------------------------------------------------
extern "C" void kernel_launch(void* const* d_in, const int* in_sizes, int n_in,
                              void* d_out, int out_size)
{
    const float* w      = (const float*)d_in[0];
    const float* r      = (const float*)d_in[1];
    const float* rwb    = (const float*)d_in[2];
    const float* rrb    = (const float*)d_in[3];
    // d_in[4] = attn_mask (causal triu, implicit)
    const float* qkv_w  = (const float*)d_in[5];
    const float* rnet_w = (const float*)d_in[6];
    const float* o_w    = (const float*)d_in[7];
    const float* ln1_g  = (const float*)d_in[8];
    const float* ln1_b  = (const float*)d_in[9];
    const float* ffn_w1 = (const float*)d_in[10];
    const float* ffn_b1 = (const float*)d_in[11];
    const float* ffn_w2 = (const float*)d_in[12];
    const float* ffn_b2 = (const float*)d_in[13];
    const float* ln2_g  = (const float*)d_in[14];
    const float* ln2_b  = (const float*)d_in[15];

    float *heads, *rk, *attnvec, *attnout, *x, *h, *core;
    cudaGetSymbolAddress((void**)&heads,   g_heads);
    cudaGetSymbolAddress((void**)&rk,      g_rk);
    cudaGetSymbolAddress((void**)&attnvec, g_attnvec);
    cudaGetSymbolAddress((void**)&attnout, g_attnout);
    cudaGetSymbolAddress((void**)&x,       g_x);
    cudaGetSymbolAddress((void**)&h,       g_h);
    cudaGetSymbolAddress((void**)&core,    g_core);

    // 1) qkv projection: [4096,1024] @ [1024,3072]
    gemm_tf32<0><<<dim3(3 * DM / 128, NTOK / 128), 256>>>(w, qkv_w, heads, nullptr,
                                                          NTOK, 3 * DM, DM);
    // 2) r_k: [2048,1024] @ [1024,1024]
    gemm_tf32<0><<<dim3(DM / 128, QL / 128), 256>>>(r, rnet_w, rk, nullptr,
                                                    QL, DM, DM);
    // 3) attention (tf32 mma flash)
    {
        const int smem = (5 * 64 * ATT_STR + 128 * ATT_STR + 64 * GS_STR + 128)
                         * (int)sizeof(float);
        cudaFuncSetAttribute(attn_mma_kernel,
                             cudaFuncAttributeMaxDynamicSharedMemorySize, smem);
        attn_mma_kernel<<<dim3(QL / 64, NH, BSZ), 256, smem>>>(rwb, rrb);
    }
    // 4) o projection
    gemm_tf32<0><<<dim3(DM / 128, NTOK / 128), 256>>>(attnvec, o_w, attnout, nullptr,
                                                      NTOK, DM, DM);
    // 5) x = LN(w + attn_out)
    ln_kernel<<<NTOK, 256>>>(w, attnout, nullptr, ln1_g, ln1_b, x);
    // 6) h = relu(x @ ffn_w1 + b1)
    gemm_tf32<1><<<dim3(DI / 128, NTOK / 128), 256>>>(x, ffn_w1, h, ffn_b1,
                                                      NTOK, DI, DM);
    // 7) core = h @ ffn_w2  (bias b2 added in LN)
    gemm_tf32<0><<<dim3(DM / 128, NTOK / 128), 256>>>(h, ffn_w2, core, nullptr,
                                                      NTOK, DM, DI);
    // 8) out = LN(x + core + b2)
    ln_kernel<<<NTOK, 256>>>(x, core, ffn_b2, ln2_g, ln2_b, (float*)d_out);
}